// round 9
// baseline (speedup 1.0000x reference)
#include <cuda_runtime.h>
#include <cuda_pipeline.h>
#include <mma.h>
#include <math.h>

using namespace nvcuda;

#define BATCH  64
#define SEQ    512
#define INSZ   1024
#define HID    1024
#define G4     4096
#define BSH    (BATCH * SEQ * HID)
#define CTAS   128
#define THREADS 256
#define HB     8           // hidden units per CTA
#define NC     32          // gate-columns per CTA (4 gates x 8)
#define SWP    34          // sW row pitch (floats)
#define ACP    33          // sAcc row pitch (floats)
#define SAP    36          // gemm sA pitch
#define SBP    132         // gemm sB pitch

// Scratch (device globals: allocation-free per harness rules)
__device__ float g_Gx[(size_t)SEQ * BATCH * G4];   // [t][b][4096] = 512 MB
__device__ unsigned g_bar[SEQ];                    // per-step barrier counters
__device__ float2 g_blist[3][BATCH][HID];          // triple-buffered per-b record lists
__device__ int    g_lcnt[3][BATCH];                // list counters

// ---------------------------------------------------------------------------
// Phase 1: Gx = X @ Wx (4 gates), tf32 wmma 128x128 tile, BK=32,
// 2-stage cp.async double buffering. Block (0,0) also re-inits the
// barrier/counter state (replaces the separate k_init launch).
// ---------------------------------------------------------------------------
__global__ __launch_bounds__(256) void k_gemm_x(
    const float* __restrict__ x,
    const float* __restrict__ Wf, const float* __restrict__ Wi,
    const float* __restrict__ Wc, const float* __restrict__ Wo)
{
    extern __shared__ float dsm[];
    float (*sA)[128][SAP] = (float(*)[128][SAP])dsm;                    // 2 stages
    float (*sB)[32][SBP]  = (float(*)[32][SBP])(dsm + 2 * 128 * SAP);

    const int tid  = threadIdx.x;

    if (blockIdx.x == 0 && blockIdx.y == 0) {      // state re-init for k_lstm
        for (int i = tid; i < SEQ; i += 256) g_bar[i] = 0u;
        for (int i = tid; i < 3 * BATCH; i += 256) (&g_lcnt[0][0])[i] = 0;
    }

    const int bn = blockIdx.x;
    const int bm = blockIdx.y;
    const int gate = bn >> 3;
    const int c0 = (bn & 7) * 128;
    const float* W = (gate == 0) ? Wf : (gate == 1) ? Wi : (gate == 2) ? Wc : Wo;

    const int warp = tid >> 5;
    const int wm   = warp & 3;
    const int wn   = warp >> 2;

    auto issue = [&](int stage, int kc) {
#pragma unroll
        for (int l = 0; l < 4; l++) {
            int f = tid + l * 256;
            int r = f >> 3, c4 = f & 7;
            __pipeline_memcpy_async(&sA[stage][r][c4 * 4],
                x + (size_t)(bm * 128 + r) * 1024 + kc * 32 + c4 * 4, 16);
        }
#pragma unroll
        for (int l = 0; l < 4; l++) {
            int f = tid + l * 256;
            int kr = f >> 5, c4 = f & 31;
            __pipeline_memcpy_async(&sB[stage][kr][c4 * 4],
                W + (size_t)(1024 + kc * 32 + kr) * 1024 + c0 + c4 * 4, 16);
        }
        __pipeline_commit();
    };

    wmma::fragment<wmma::accumulator, 16, 16, 8, float> acc[2][4];
#pragma unroll
    for (int i = 0; i < 2; i++)
#pragma unroll
        for (int j = 0; j < 4; j++) wmma::fill_fragment(acc[i][j], 0.f);

    issue(0, 0);
    for (int kc = 0; kc < 32; ++kc) {
        if (kc + 1 < 32) {
            issue((kc + 1) & 1, kc + 1);
            __pipeline_wait_prior(1);
        } else {
            __pipeline_wait_prior(0);
        }
        __syncthreads();

        const int st = kc & 1;
#pragma unroll
        for (int kk = 0; kk < 4; ++kk) {
            wmma::fragment<wmma::matrix_a, 16, 16, 8, wmma::precision::tf32, wmma::row_major> af[2];
            wmma::fragment<wmma::matrix_b, 16, 16, 8, wmma::precision::tf32, wmma::row_major> bfr[4];
#pragma unroll
            for (int i = 0; i < 2; i++) {
                wmma::load_matrix_sync(af[i], &sA[st][wm * 32 + i * 16][kk * 8], SAP);
#pragma unroll
                for (int e = 0; e < af[i].num_elements; e++)
                    af[i].x[e] = wmma::__float_to_tf32(af[i].x[e]);
            }
#pragma unroll
            for (int j = 0; j < 4; j++) {
                wmma::load_matrix_sync(bfr[j], &sB[st][kk * 8][wn * 64 + j * 16], SBP);
#pragma unroll
                for (int e = 0; e < bfr[j].num_elements; e++)
                    bfr[j].x[e] = wmma::__float_to_tf32(bfr[j].x[e]);
            }
#pragma unroll
            for (int i = 0; i < 2; i++)
#pragma unroll
                for (int j = 0; j < 4; j++)
                    wmma::mma_sync(acc[i][j], af[i], bfr[j], acc[i][j]);
        }
        __syncthreads();
    }

#pragma unroll
    for (int i = 0; i < 2; i++) {
        int m0 = bm * 128 + wm * 32 + i * 16;
        int bidx = m0 >> 9;
        int t0 = m0 & 511;
        float* rowbase = g_Gx + (size_t)(t0 * 64 + bidx) * G4 + gate * 1024 + c0 + wn * 64;
#pragma unroll
        for (int j = 0; j < 4; j++)
            wmma::store_matrix_sync(rowbase + j * 16, acc[i][j],
                                    (unsigned)(64 * G4), wmma::mem_row_major);
    }
}

// ---------------------------------------------------------------------------
// Phase 2: persistent kernel, NO dense path. sAcc starts at 0 == Wh @ 0;
// every step applies exact fp32 rank-1 cummax-record updates (t=0 emits all
// 1024 deltas per b at deterministic positions). Pure-spin grid barrier.
// ---------------------------------------------------------------------------
__device__ __forceinline__ float sigf(float v) {
    return __fdividef(1.f, 1.f + __expf(-v));
}
__device__ __forceinline__ float tanhfast(float v) {
    float ex = __expf(2.f * v);
    return 1.f - __fdividef(2.f, ex + 1.f);
}

__global__ __launch_bounds__(THREADS, 1) void k_lstm(
    const float* __restrict__ Wf, const float* __restrict__ Wi,
    const float* __restrict__ Wc, const float* __restrict__ Wo,
    const float* __restrict__ bfv, const float* __restrict__ biv,
    const float* __restrict__ bcv, const float* __restrict__ bov,
    float* __restrict__ out)
{
    extern __shared__ float smem[];
    float* sW   = smem;                         // [1024][SWP] fp32 weights (resident)
    float* sAcc = smem + 1024 * SWP;            // [64][ACP] recurrent accumulator

    __shared__ float sBias[NC];

    const int tid  = threadIdx.x;
    const int warp = tid >> 5;
    const int lane = tid & 31;
    const int h0   = blockIdx.x * HB;

    // ---- one-time: preload this CTA's 32 weight columns; zero sAcc ----
    for (int k = tid; k < 1024; k += THREADS) {
#pragma unroll
        for (int g = 0; g < 4; g++) {
            const float* W = (g == 0) ? Wf : (g == 1) ? Wi : (g == 2) ? Wc : Wo;
            float4 v0 = *reinterpret_cast<const float4*>(W + (size_t)k * 1024 + h0);
            float4 v1 = *reinterpret_cast<const float4*>(W + (size_t)k * 1024 + h0 + 4);
            float* d = &sW[k * SWP + g * 8];
            d[0] = v0.x; d[1] = v0.y; d[2] = v0.z; d[3] = v0.w;
            d[4] = v1.x; d[5] = v1.y; d[6] = v1.z; d[7] = v1.w;
        }
    }
    for (int i = tid; i < 64 * ACP; i += THREADS) sAcc[i] = 0.f;
    if (tid < NC) {
        int g = tid >> 3, hh = tid & 7;
        const float* bv = (g == 0) ? bfv : (g == 1) ? biv : (g == 2) ? bcv : bov;
        sBias[tid] = bv[h0 + hh];
    }
    __syncthreads();

    float creg[2] = {0.f, 0.f};
    float hreg[2] = {0.f, 0.f};

    // software-pipelined Gx prefetch (t = 0)
    float gx[2][4];
#pragma unroll
    for (int l = 0; l < 2; l++) {
        int e = tid + l * THREADS;
        int b = e >> 3, hh = e & 7;
        const float* gp = g_Gx + (size_t)b * G4 + h0 + hh;
#pragma unroll
        for (int g = 0; g < 4; g++) gx[l][g] = __ldcg(gp + g * 1024);
    }

    for (int t = 0; t < SEQ; ++t) {
        // reset counter for the dead phase (consumed two steps from now)
        if (blockIdx.x < BATCH && tid == 0)
            atomicExch(&g_lcnt[(t + 1) % 3][blockIdx.x], 0);

        // ---- sparse apply: warp w owns b in [8w, 8w+8) ----
        if (t > 0) {
            const int ph = (t + 2) % 3;                  // == (t-1) % 3
            const int b0 = warp << 3;
            int myc = (lane < 8) ? __ldcg(&g_lcnt[ph][b0 + lane]) : 0;
            int n[8];
            int nmax = 0;
#pragma unroll
            for (int bb = 0; bb < 8; bb++) {
                n[bb] = __shfl_sync(0xffffffffu, myc, bb);
                nmax = max(nmax, n[bb]);
            }
            float acc8[8];
#pragma unroll
            for (int bb = 0; bb < 8; bb++)
                acc8[bb] = sAcc[(b0 + bb) * ACP + lane];

            for (int e = 0; e < nmax; ++e) {
#pragma unroll
                for (int bb = 0; bb < 8; bb++) {
                    if (e < n[bb]) {
                        float2 E = __ldcg(&g_blist[ph][b0 + bb][e]);
                        acc8[bb] += E.y * sW[__float_as_int(E.x) * SWP + lane];
                    }
                }
            }
#pragma unroll
            for (int bb = 0; bb < 8; bb++)
                sAcc[(b0 + bb) * ACP + lane] = acc8[bb];
            __syncthreads();
        }

        // ---- elementwise: gates, state, cummax, record emission ----
        float outv[2];
        bool emitted = (t == 0);
#pragma unroll
        for (int l = 0; l < 2; l++) {
            int e  = tid + l * THREADS;      // 0..511
            int b  = e >> 3, hh = e & 7;
            int h  = h0 + hh;

            float s0 = sAcc[b * ACP + hh];
            float s1 = sAcc[b * ACP + 8 + hh];
            float s2 = sAcc[b * ACP + 16 + hh];
            float s3 = sAcc[b * ACP + 24 + hh];

            float gf = s0 + gx[l][0] + sBias[hh];
            float gi = s1 + gx[l][1] + sBias[8 + hh];
            float gc = s2 + gx[l][2] + sBias[16 + hh];
            float go = s3 + gx[l][3] + sBias[24 + hh];

            float Cn = sigf(gf) * creg[l] + sigf(gi) * tanhfast(gc);
            creg[l] = Cn;
            float hv = sigf(go) * tanhfast(Cn);
            outv[l] = hv;

            if (t == 0) {
                // hmax_0 = h_0 (prev is -inf): emit delta = hv at slot h. No atomics.
                g_blist[0][b][h] = make_float2(__int_as_float(h), hv);
            } else if (t < SEQ - 1 && hv > hreg[l]) {
                float dlt = hv - hreg[l];
                int pos = atomicAdd(&g_lcnt[t % 3][b], 1);
                g_blist[t % 3][b][pos] = make_float2(__int_as_float(h), dlt);
                emitted = true;
            }
            float hm = (t == 0) ? hv : fmaxf(hreg[l], hv);
            hreg[l] = hm;

            if (t == SEQ - 1) {
                out[(size_t)b * SEQ * HID + (size_t)t * HID + h] = hv;
                out[(size_t)BSH + b * HID + h] = hm;                     // h_fin
                out[(size_t)BSH + BATCH * HID + b * HID + h] = Cn;       // C_fin
            }
        }
        if (t == 0 && blockIdx.x < BATCH && tid == 0)
            g_lcnt[0][blockIdx.x] = HID;     // exactly 1024 records at t=0

        if (t < SEQ - 1) {
            if (emitted) __threadfence();    // release this thread's record stores
            __syncthreads();
            if (tid == 0) atomicAdd(&g_bar[t], 1u);

            // ---- work hidden under the barrier wait ----
#pragma unroll
            for (int l = 0; l < 2; l++) {
                int e = tid + l * THREADS;
                int b = e >> 3, hh = e & 7;
                out[(size_t)b * SEQ * HID + (size_t)t * HID + h0 + hh] = outv[l];
            }
#pragma unroll
            for (int l = 0; l < 2; l++) {
                int e = tid + l * THREADS;
                int b = e >> 3, hh = e & 7;
                const float* gp = g_Gx + (size_t)((t + 1) * 64 + b) * G4 + h0 + hh;
#pragma unroll
                for (int g = 0; g < 4; g++) gx[l][g] = __ldcg(gp + g * 1024);
            }

            if (tid == 0) {
                volatile unsigned* p = &g_bar[t];
                while (*p < (unsigned)CTAS) { }      // pure spin, no nanosleep
            }
            __syncthreads();
        }
    }
}

extern "C" void kernel_launch(void* const* d_in, const int* in_sizes, int n_in,
                              void* d_out, int out_size) {
    const float* x  = (const float*)d_in[0];
    const float* Wf = (const float*)d_in[1];
    const float* bf = (const float*)d_in[2];
    const float* Wi = (const float*)d_in[3];
    const float* bi = (const float*)d_in[4];
    const float* Wc = (const float*)d_in[5];
    const float* bc = (const float*)d_in[6];
    const float* Wo = (const float*)d_in[7];
    const float* bo = (const float*)d_in[8];
    float* out = (float*)d_out;

    static const size_t SMEM_L = (1024 * SWP + 64 * ACP) * sizeof(float);  // 147,712 B
    static const size_t SMEM_G = (2 * 128 * SAP + 2 * 32 * SBP) * sizeof(float);
    cudaFuncSetAttribute(k_lstm,   cudaFuncAttributeMaxDynamicSharedMemorySize, (int)SMEM_L);
    cudaFuncSetAttribute(k_gemm_x, cudaFuncAttributeMaxDynamicSharedMemorySize, (int)SMEM_G);

    k_gemm_x<<<dim3(32, 256), 256, SMEM_G>>>(x, Wf, Wi, Wc, Wo);
    k_lstm<<<CTAS, THREADS, SMEM_L>>>(Wf, Wi, Wc, Wo, bf, bi, bc, bo, out);
}

// round 11
// speedup vs baseline: 1.3812x; 1.3812x over previous
#include <cuda_runtime.h>
#include <cuda_pipeline.h>
#include <mma.h>
#include <math.h>

using namespace nvcuda;

#define BATCH  64
#define SEQ    512
#define INSZ   1024
#define HID    1024
#define G4     4096
#define BSH    (BATCH * SEQ * HID)
#define CTAS   128
#define THREADS 256
#define HB     8           // hidden units per CTA
#define NC     32          // gate-columns per CTA (4 gates x 8)
#define SWP    34          // sW row pitch (floats)
#define SPP    34          // sP row pitch (floats)
#define ACP    33          // sAcc row pitch (floats)
#define TD     16          // dense warmup steps
#define SAP    36          // gemm sA pitch
#define SBP    132         // gemm sB pitch

// Scratch (device globals: allocation-free per harness rules)
__device__ float g_Gx[(size_t)SEQ * BATCH * G4];   // [t][b][4096] = 512 MB
__device__ float g_hbuf[2][BATCH * HID];           // ping-pong hmax (dense steps only)
__device__ unsigned g_bar[SEQ];                    // arrival counters
__device__ unsigned g_rel[SEQ];                    // release flags (separate lines!)
__device__ float2 g_blist[3][BATCH][HID];          // triple-buffered per-b record lists
__device__ int    g_lcnt[3][BATCH];                // list counters

// ---------------------------------------------------------------------------
// Phase 1: Gx = X @ Wx (4 gates), tf32 wmma 128x128 tile, BK=32,
// 2-stage cp.async double buffering. Block (0,0) re-inits persistent state.
// ---------------------------------------------------------------------------
__global__ __launch_bounds__(256) void k_gemm_x(
    const float* __restrict__ x,
    const float* __restrict__ Wf, const float* __restrict__ Wi,
    const float* __restrict__ Wc, const float* __restrict__ Wo)
{
    extern __shared__ float dsm[];
    float (*sA)[128][SAP] = (float(*)[128][SAP])dsm;
    float (*sB)[32][SBP]  = (float(*)[32][SBP])(dsm + 2 * 128 * SAP);

    const int tid  = threadIdx.x;

    if (blockIdx.x == 0 && blockIdx.y == 0) {      // state re-init for k_lstm
        for (int i = tid; i < SEQ; i += 256) { g_bar[i] = 0u; g_rel[i] = 0u; }
        for (int i = tid; i < 3 * BATCH; i += 256) (&g_lcnt[0][0])[i] = 0;
    }

    const int bn = blockIdx.x;
    const int bm = blockIdx.y;
    const int gate = bn >> 3;
    const int c0 = (bn & 7) * 128;
    const float* W = (gate == 0) ? Wf : (gate == 1) ? Wi : (gate == 2) ? Wc : Wo;

    const int warp = tid >> 5;
    const int wm   = warp & 3;
    const int wn   = warp >> 2;

    auto issue = [&](int stage, int kc) {
#pragma unroll
        for (int l = 0; l < 4; l++) {
            int f = tid + l * 256;
            int r = f >> 3, c4 = f & 7;
            __pipeline_memcpy_async(&sA[stage][r][c4 * 4],
                x + (size_t)(bm * 128 + r) * 1024 + kc * 32 + c4 * 4, 16);
        }
#pragma unroll
        for (int l = 0; l < 4; l++) {
            int f = tid + l * 256;
            int kr = f >> 5, c4 = f & 31;
            __pipeline_memcpy_async(&sB[stage][kr][c4 * 4],
                W + (size_t)(1024 + kc * 32 + kr) * 1024 + c0 + c4 * 4, 16);
        }
        __pipeline_commit();
    };

    wmma::fragment<wmma::accumulator, 16, 16, 8, float> acc[2][4];
#pragma unroll
    for (int i = 0; i < 2; i++)
#pragma unroll
        for (int j = 0; j < 4; j++) wmma::fill_fragment(acc[i][j], 0.f);

    issue(0, 0);
    for (int kc = 0; kc < 32; ++kc) {
        if (kc + 1 < 32) {
            issue((kc + 1) & 1, kc + 1);
            __pipeline_wait_prior(1);
        } else {
            __pipeline_wait_prior(0);
        }
        __syncthreads();

        const int st = kc & 1;
#pragma unroll
        for (int kk = 0; kk < 4; ++kk) {
            wmma::fragment<wmma::matrix_a, 16, 16, 8, wmma::precision::tf32, wmma::row_major> af[2];
            wmma::fragment<wmma::matrix_b, 16, 16, 8, wmma::precision::tf32, wmma::row_major> bfr[4];
#pragma unroll
            for (int i = 0; i < 2; i++) {
                wmma::load_matrix_sync(af[i], &sA[st][wm * 32 + i * 16][kk * 8], SAP);
#pragma unroll
                for (int e = 0; e < af[i].num_elements; e++)
                    af[i].x[e] = wmma::__float_to_tf32(af[i].x[e]);
            }
#pragma unroll
            for (int j = 0; j < 4; j++) {
                wmma::load_matrix_sync(bfr[j], &sB[st][kk * 8][wn * 64 + j * 16], SBP);
#pragma unroll
                for (int e = 0; e < bfr[j].num_elements; e++)
                    bfr[j].x[e] = wmma::__float_to_tf32(bfr[j].x[e]);
            }
#pragma unroll
            for (int i = 0; i < 2; i++)
#pragma unroll
                for (int j = 0; j < 4; j++)
                    wmma::mma_sync(acc[i][j], af[i], bfr[j], acc[i][j]);
        }
        __syncthreads();
    }

#pragma unroll
    for (int i = 0; i < 2; i++) {
        int m0 = bm * 128 + wm * 32 + i * 16;
        int bidx = m0 >> 9;
        int t0 = m0 & 511;
        float* rowbase = g_Gx + (size_t)(t0 * 64 + bidx) * G4 + gate * 1024 + c0 + wn * 64;
#pragma unroll
        for (int j = 0; j < 4; j++)
            wmma::store_matrix_sync(rowbase + j * 16, acc[i][j],
                                    (unsigned)(64 * G4), wmma::mem_row_major);
    }
}

// ---------------------------------------------------------------------------
// Phase 2: persistent kernel. Dense tf32 warmup (t<TD) seeds fp32 accumulator;
// then exact sparse rank-1 cummax-record updates with coalesced, staged,
// prefetched apply. Release-flag grid barrier (polls read-only line).
// ---------------------------------------------------------------------------
__device__ __forceinline__ float sigf(float v) {
    return __fdividef(1.f, 1.f + __expf(-v));
}
__device__ __forceinline__ float tanhfast(float v) {
    float ex = __expf(2.f * v);
    return 1.f - __fdividef(2.f, ex + 1.f);
}

__global__ __launch_bounds__(THREADS, 1) void k_lstm(
    const float* __restrict__ Wf, const float* __restrict__ Wi,
    const float* __restrict__ Wc, const float* __restrict__ Wo,
    const float* __restrict__ bfv, const float* __restrict__ biv,
    const float* __restrict__ bcv, const float* __restrict__ bov,
    float* __restrict__ out)
{
    extern __shared__ float smem[];
    float*  sW    = smem;                          // [1024][SWP] fp32 weights
    float*  sP    = smem + 1024 * SWP;             // [8][64][SPP] dense partials
    float*  sAcc  = sP + 8 * 64 * SPP;             // [64][ACP] accumulator
    float2* sStg  = (float2*)(sAcc + 64 * ACP);    // [8][32] apply staging

    __shared__ float sBias[NC];

    const int tid  = threadIdx.x;
    const int warp = tid >> 5;
    const int lane = tid & 31;
    const int h0   = blockIdx.x * HB;

    for (int k = tid; k < 1024; k += THREADS) {
#pragma unroll
        for (int g = 0; g < 4; g++) {
            const float* W = (g == 0) ? Wf : (g == 1) ? Wi : (g == 2) ? Wc : Wo;
            float4 v0 = *reinterpret_cast<const float4*>(W + (size_t)k * 1024 + h0);
            float4 v1 = *reinterpret_cast<const float4*>(W + (size_t)k * 1024 + h0 + 4);
            float* d = &sW[k * SWP + g * 8];
            d[0] = v0.x; d[1] = v0.y; d[2] = v0.z; d[3] = v0.w;
            d[4] = v1.x; d[5] = v1.y; d[6] = v1.z; d[7] = v1.w;
        }
    }
    if (tid < NC) {
        int g = tid >> 3, hh = tid & 7;
        const float* bv = (g == 0) ? bfv : (g == 1) ? biv : (g == 2) ? bcv : bov;
        sBias[tid] = bv[h0 + hh];
    }
    __syncthreads();

    float creg[2] = {0.f, 0.f};
    float hreg[2] = {0.f, 0.f};

    // Gx prefetch (t = 0)
    float gx[2][4];
#pragma unroll
    for (int l = 0; l < 2; l++) {
        int e = tid + l * THREADS;
        int b = e >> 3, hh = e & 7;
        const float* gp = g_Gx + (size_t)b * G4 + h0 + hh;
#pragma unroll
        for (int g = 0; g < 4; g++) gx[l][g] = __ldcg(gp + g * 1024);
    }

    for (int t = 0; t < SEQ; ++t) {
        if (blockIdx.x < BATCH && tid == 0)
            atomicExch(&g_lcnt[(t + 1) % 3][blockIdx.x], 0);

        const bool dense = (t < TD);

        if (t > 0) {
            if (dense) {
                // ---- dense recurrent GEMM: K-split x8, A from global ----
                const float* __restrict__ hin = g_hbuf[(t + 1) & 1];
                const int kbase = warp * 128;

                wmma::fragment<wmma::accumulator, 16, 16, 8, float> acc[4][2];
#pragma unroll
                for (int i = 0; i < 4; i++) {
                    wmma::fill_fragment(acc[i][0], 0.f);
                    wmma::fill_fragment(acc[i][1], 0.f);
                }
#pragma unroll 4
                for (int kk = 0; kk < 16; ++kk) {
                    const int k0 = kbase + kk * 8;
                    wmma::fragment<wmma::matrix_b, 16, 16, 8, wmma::precision::tf32, wmma::row_major> bfr[2];
                    wmma::load_matrix_sync(bfr[0], &sW[k0 * SWP], SWP);
                    wmma::load_matrix_sync(bfr[1], &sW[k0 * SWP + 16], SWP);
#pragma unroll
                    for (int e = 0; e < bfr[0].num_elements; e++) {
                        bfr[0].x[e] = wmma::__float_to_tf32(bfr[0].x[e]);
                        bfr[1].x[e] = wmma::__float_to_tf32(bfr[1].x[e]);
                    }
                    wmma::fragment<wmma::matrix_a, 16, 16, 8, wmma::precision::tf32, wmma::row_major> af[4];
#pragma unroll
                    for (int i = 0; i < 4; i++) {
                        wmma::load_matrix_sync(af[i], hin + (size_t)(i * 16) * 1024 + k0, 1024);
#pragma unroll
                        for (int e = 0; e < af[i].num_elements; e++)
                            af[i].x[e] = wmma::__float_to_tf32(af[i].x[e]);
                        wmma::mma_sync(acc[i][0], af[i], bfr[0], acc[i][0]);
                        wmma::mma_sync(acc[i][1], af[i], bfr[1], acc[i][1]);
                    }
                }
#pragma unroll
                for (int i = 0; i < 4; i++)
#pragma unroll
                    for (int j = 0; j < 2; j++)
                        wmma::store_matrix_sync(&sP[warp * (64 * SPP) + (i * 16) * SPP + j * 16],
                                                acc[i][j], SPP, wmma::mem_row_major);
                __syncthreads();
            } else {
                // ---- sparse apply: coalesced + staged + prefetched ----
                const int ph = (t + 2) % 3;              // == (t-1) % 3
                const int b0 = warp << 3;
                int myc = (lane < 8) ? __ldcg(&g_lcnt[ph][b0 + lane]) : 0;
                int n[8];
#pragma unroll
                for (int bb = 0; bb < 8; bb++)
                    n[bb] = __shfl_sync(0xffffffffu, myc, bb);

                float acc8[8];
#pragma unroll
                for (int bb = 0; bb < 8; bb++)
                    acc8[bb] = sAcc[(b0 + bb) * ACP + lane];

                // prefetch first batch for all 8 b's (8 LDGs in flight)
                float2 pre[8];
#pragma unroll
                for (int bb = 0; bb < 8; bb++)
                    pre[bb] = (lane < n[bb])
                        ? __ldcg(&g_blist[ph][b0 + bb][lane])
                        : make_float2(0.f, 0.f);

                float2* stg = &sStg[warp * 32];
#pragma unroll
                for (int bb = 0; bb < 8; bb++) {
                    int nb = n[bb];
                    float2 cur = pre[bb];
                    for (int base = 0; base < nb; base += 32) {
                        stg[lane] = cur;
                        __syncwarp();
                        // prefetch next batch of this b (rare beyond 1 batch)
                        if (base + 32 < nb)
                            cur = (lane < nb - base - 32)
                                ? __ldcg(&g_blist[ph][b0 + bb][base + 32 + lane])
                                : make_float2(0.f, 0.f);
                        int cnt = min(32, nb - base);
                        for (int j = 0; j < cnt; ++j) {
                            float2 E = stg[j];               // LDS broadcast
                            acc8[bb] += E.y * sW[__float_as_int(E.x) * SWP + lane];
                        }
                        __syncwarp();
                    }
                }
#pragma unroll
                for (int bb = 0; bb < 8; bb++)
                    sAcc[(b0 + bb) * ACP + lane] = acc8[bb];
                __syncthreads();
            }
        }

        // ---- elementwise: gates, state, cummax, record emission ----
        float* __restrict__ hnew = g_hbuf[t & 1];
        float outv[2];
        bool emitted = false;
#pragma unroll
        for (int l = 0; l < 2; l++) {
            int e  = tid + l * THREADS;
            int b  = e >> 3, hh = e & 7;
            int h  = h0 + hh;

            float s0, s1, s2, s3;
            if (dense) {
                s0 = s1 = s2 = s3 = 0.f;
                if (t > 0) {
#pragma unroll
                    for (int w = 0; w < 8; w++) {
                        const float* p = &sP[w * (64 * SPP) + b * SPP];
                        s0 += p[hh];
                        s1 += p[8 + hh];
                        s2 += p[16 + hh];
                        s3 += p[24 + hh];
                    }
                }
                sAcc[b * ACP + hh]      = s0;
                sAcc[b * ACP + 8 + hh]  = s1;
                sAcc[b * ACP + 16 + hh] = s2;
                sAcc[b * ACP + 24 + hh] = s3;
            } else {
                s0 = sAcc[b * ACP + hh];
                s1 = sAcc[b * ACP + 8 + hh];
                s2 = sAcc[b * ACP + 16 + hh];
                s3 = sAcc[b * ACP + 24 + hh];
            }

            float gf = s0 + gx[l][0] + sBias[hh];
            float gi = s1 + gx[l][1] + sBias[8 + hh];
            float gc = s2 + gx[l][2] + sBias[16 + hh];
            float go = s3 + gx[l][3] + sBias[24 + hh];

            float Cn = sigf(gf) * creg[l] + sigf(gi) * tanhfast(gc);
            creg[l] = Cn;
            float hv = sigf(go) * tanhfast(Cn);
            outv[l] = hv;

            if (t >= TD - 1 && t < SEQ - 1 && hv > hreg[l]) {
                float dlt = hv - hreg[l];
                int pos = atomicAdd(&g_lcnt[t % 3][b], 1);
                g_blist[t % 3][b][pos] = make_float2(__int_as_float(h), dlt);
                emitted = true;
            }
            float hm = (t == 0) ? hv : fmaxf(hreg[l], hv);
            hreg[l] = hm;

            if (t < TD - 1) hnew[b * HID + h] = hm;

            if (t == SEQ - 1) {
                out[(size_t)b * SEQ * HID + (size_t)t * HID + h] = hv;
                out[(size_t)BSH + b * HID + h] = hm;                     // h_fin
                out[(size_t)BSH + BATCH * HID + b * HID + h] = Cn;       // C_fin
            }
        }

        if (t < SEQ - 1) {
            if (dense || emitted) __threadfence();   // release payload stores
            __syncthreads();
            unsigned arr = 0;
            if (tid == 0) arr = atomicAdd(&g_bar[t], 1u) + 1;

            // ---- work hidden under the barrier ----
#pragma unroll
            for (int l = 0; l < 2; l++) {
                int e = tid + l * THREADS;
                int b = e >> 3, hh = e & 7;
                out[(size_t)b * SEQ * HID + (size_t)t * HID + h0 + hh] = outv[l];
            }
#pragma unroll
            for (int l = 0; l < 2; l++) {
                int e = tid + l * THREADS;
                int b = e >> 3, hh = e & 7;
                const float* gp = g_Gx + (size_t)((t + 1) * 64 + b) * G4 + h0 + hh;
#pragma unroll
                for (int g = 0; g < 4; g++) gx[l][g] = __ldcg(gp + g * 1024);
            }

            if (tid == 0) {
                if (arr == CTAS) {
                    __stcg(&g_rel[t], 1u);           // release flag (own line)
                } else {
                    volatile unsigned* p = &g_rel[t];
                    while (*p == 0u) { }             // poll read-only line
                }
                if (t + 1 < TD) __threadfence();     // L1 inval for dense readers
            }
            __syncthreads();
        }
    }
}

extern "C" void kernel_launch(void* const* d_in, const int* in_sizes, int n_in,
                              void* d_out, int out_size) {
    const float* x  = (const float*)d_in[0];
    const float* Wf = (const float*)d_in[1];
    const float* bf = (const float*)d_in[2];
    const float* Wi = (const float*)d_in[3];
    const float* bi = (const float*)d_in[4];
    const float* Wc = (const float*)d_in[5];
    const float* bc = (const float*)d_in[6];
    const float* Wo = (const float*)d_in[7];
    const float* bo = (const float*)d_in[8];
    float* out = (float*)d_out;

    static const size_t SMEM_L =
        (1024 * SWP + 8 * 64 * SPP + 64 * ACP) * sizeof(float) + 8 * 32 * sizeof(float2);
    static const size_t SMEM_G = (2 * 128 * SAP + 2 * 32 * SBP) * sizeof(float);
    cudaFuncSetAttribute(k_lstm,   cudaFuncAttributeMaxDynamicSharedMemorySize, (int)SMEM_L);
    cudaFuncSetAttribute(k_gemm_x, cudaFuncAttributeMaxDynamicSharedMemorySize, (int)SMEM_G);

    k_gemm_x<<<dim3(32, 256), 256, SMEM_G>>>(x, Wf, Wi, Wc, Wo);
    k_lstm<<<CTAS, THREADS, SMEM_L>>>(Wf, Wi, Wc, Wo, bf, bi, bc, bo, out);
}

// round 12
// speedup vs baseline: 1.6389x; 1.1866x over previous
#include <cuda_runtime.h>
#include <cuda_pipeline.h>
#include <cuda_bf16.h>
#include <mma.h>
#include <math.h>

using namespace nvcuda;

#define BATCH  64
#define SEQ    512
#define INSZ   1024
#define HID    1024
#define G4     4096
#define BSH    (BATCH * SEQ * HID)
#define CTAS   128
#define THREADS 256
#define HB     8           // hidden units per CTA
#define NC     32          // gate-columns per CTA (4 gates x 8)
#define SWP    34          // sW row pitch (floats)
#define SPP    34          // sP row pitch (floats)
#define ACP    33          // sAcc row pitch (floats)
#define TD     16          // dense warmup steps
#define XAP    40          // gemm bf16 A pitch (bf16 elems)
#define XBP    136         // gemm bf16 B pitch (bf16 elems)

// Scratch (device globals: allocation-free per harness rules)
__device__ float g_Gx[(size_t)SEQ * BATCH * G4];   // [t][b][4096] = 512 MB
__device__ float g_hbuf[2][BATCH * HID];           // ping-pong hmax (dense steps only)
__device__ unsigned g_bar[SEQ];                    // arrival counters
__device__ unsigned g_rel[SEQ];                    // release flags (separate lines)
__device__ float2 g_blist[3][BATCH][HID];          // triple-buffered per-b record lists
__device__ int    g_lcnt[3][BATCH];                // list counters
// split-bf16 planes for the big GEMM
__device__ __nv_bfloat16 g_xh[(size_t)BATCH * SEQ * INSZ];   // 64 MB
__device__ __nv_bfloat16 g_xl[(size_t)BATCH * SEQ * INSZ];   // 64 MB
__device__ __nv_bfloat16 g_wh[(size_t)INSZ * G4];            // 8 MB  [k][gate*1024+c]
__device__ __nv_bfloat16 g_wl[(size_t)INSZ * G4];            // 8 MB

// ---------------------------------------------------------------------------
// Phase 0: split x and W(x-part) into bf16 hi/lo planes; re-init state.
// ---------------------------------------------------------------------------
__global__ __launch_bounds__(256) void k_cvt(
    const float* __restrict__ x,
    const float* __restrict__ Wf, const float* __restrict__ Wi,
    const float* __restrict__ Wc, const float* __restrict__ Wo)
{
    const int tid = threadIdx.x;
    if (blockIdx.x == 0) {
        for (int i = tid; i < SEQ; i += 256) { g_bar[i] = 0u; g_rel[i] = 0u; }
        for (int i = tid; i < 3 * BATCH; i += 256) (&g_lcnt[0][0])[i] = 0;
    }
    const size_t NX = (size_t)BATCH * SEQ * INSZ;          // 32M
    const size_t NW = (size_t)INSZ * G4;                   // 4M
    const size_t stride = (size_t)gridDim.x * 256;
    for (size_t i = blockIdx.x * 256ull + tid; i < NX; i += stride) {
        float v = x[i];
        __nv_bfloat16 h = __float2bfloat16(v);
        g_xh[i] = h;
        g_xl[i] = __float2bfloat16(v - __bfloat162float(h));
    }
    for (size_t i = blockIdx.x * 256ull + tid; i < NW; i += stride) {
        int k = (int)(i >> 12);            // 0..1023
        int col = (int)(i & 4095);         // gate*1024 + c
        int g = col >> 10, c = col & 1023;
        const float* W = (g == 0) ? Wf : (g == 1) ? Wi : (g == 2) ? Wc : Wo;
        float v = W[(size_t)(1024 + k) * 1024 + c];
        __nv_bfloat16 h = __float2bfloat16(v);
        g_wh[i] = h;
        g_wl[i] = __float2bfloat16(v - __bfloat162float(h));
    }
}

// ---------------------------------------------------------------------------
// Phase 1: Gx = X @ Wx via split-bf16 (hi+lo), fp32 accum.
// 128x128 tile, BK=32, 2-stage cp.async. 3 MMA products per frag pair
// (hh, hl, lh); lo*lo dropped (|err| ~ 2^-16 relative).
// ---------------------------------------------------------------------------
__global__ __launch_bounds__(256) void k_gemm_x()
{
    extern __shared__ __nv_bfloat16 bsm[];
    __nv_bfloat16 (*sAh)[128][XAP] = (__nv_bfloat16(*)[128][XAP])bsm;
    __nv_bfloat16 (*sAl)[128][XAP] = (__nv_bfloat16(*)[128][XAP])(bsm + 2 * 128 * XAP);
    __nv_bfloat16 (*sBh)[32][XBP]  = (__nv_bfloat16(*)[32][XBP]) (bsm + 4 * 128 * XAP);
    __nv_bfloat16 (*sBl)[32][XBP]  = (__nv_bfloat16(*)[32][XBP]) (bsm + 4 * 128 * XAP + 2 * 32 * XBP);

    const int tid  = threadIdx.x;
    const int bn = blockIdx.x;                 // 0..31 (N tiles of 128)
    const int bm = blockIdx.y;                 // 0..255 (M tiles of 128)
    const int c0 = bn * 128;

    const int warp = tid >> 5;
    const int wm   = warp & 3;                 // m offset wm*32
    const int wn   = warp >> 2;                // n offset wn*64

    auto issue = [&](int stage, int kc) {
        // A planes: 128 rows x 32 bf16 = 4 x 16B chunks/row, 512 chunks/plane
#pragma unroll
        for (int l = 0; l < 2; l++) {
            int f = tid + l * 256;                       // 0..511
            int r = f >> 2, c = f & 3;
            size_t src = (size_t)(bm * 128 + r) * 1024 + kc * 32 + c * 8;
            __pipeline_memcpy_async(&sAh[stage][r][c * 8], g_xh + src, 16);
            __pipeline_memcpy_async(&sAl[stage][r][c * 8], g_xl + src, 16);
        }
        // B planes: 32 rows x 128 bf16 = 16 chunks/row, 512 chunks/plane
#pragma unroll
        for (int l = 0; l < 2; l++) {
            int f = tid + l * 256;
            int kr = f >> 4, c = f & 15;
            size_t src = (size_t)(kc * 32 + kr) * G4 + c0 + c * 8;
            __pipeline_memcpy_async(&sBh[stage][kr][c * 8], g_wh + src, 16);
            __pipeline_memcpy_async(&sBl[stage][kr][c * 8], g_wl + src, 16);
        }
        __pipeline_commit();
    };

    wmma::fragment<wmma::accumulator, 16, 16, 16, float> acc[2][4];
#pragma unroll
    for (int i = 0; i < 2; i++)
#pragma unroll
        for (int j = 0; j < 4; j++) wmma::fill_fragment(acc[i][j], 0.f);

    issue(0, 0);
    for (int kc = 0; kc < 32; ++kc) {
        if (kc + 1 < 32) {
            issue((kc + 1) & 1, kc + 1);
            __pipeline_wait_prior(1);
        } else {
            __pipeline_wait_prior(0);
        }
        __syncthreads();

        const int st = kc & 1;
#pragma unroll
        for (int kk = 0; kk < 2; ++kk) {           // 2 x k16 per kc
            const int k0 = kk * 16;
            wmma::fragment<wmma::matrix_a, 16, 16, 16, __nv_bfloat16, wmma::row_major> ah[2], al[2];
            wmma::fragment<wmma::matrix_b, 16, 16, 16, __nv_bfloat16, wmma::row_major> bh[4], bl[4];
#pragma unroll
            for (int i = 0; i < 2; i++) {
                wmma::load_matrix_sync(ah[i], &sAh[st][wm * 32 + i * 16][k0], XAP);
                wmma::load_matrix_sync(al[i], &sAl[st][wm * 32 + i * 16][k0], XAP);
            }
#pragma unroll
            for (int j = 0; j < 4; j++) {
                wmma::load_matrix_sync(bh[j], &sBh[st][k0][wn * 64 + j * 16], XBP);
                wmma::load_matrix_sync(bl[j], &sBl[st][k0][wn * 64 + j * 16], XBP);
            }
#pragma unroll
            for (int i = 0; i < 2; i++)
#pragma unroll
                for (int j = 0; j < 4; j++) {
                    wmma::mma_sync(acc[i][j], ah[i], bh[j], acc[i][j]);
                    wmma::mma_sync(acc[i][j], ah[i], bl[j], acc[i][j]);
                    wmma::mma_sync(acc[i][j], al[i], bh[j], acc[i][j]);
                }
        }
        __syncthreads();
    }

    // Store with row remap m = b*512 + t -> out row t*64 + b (stride folded in ldm)
#pragma unroll
    for (int i = 0; i < 2; i++) {
        int m0 = bm * 128 + wm * 32 + i * 16;
        int bidx = m0 >> 9;
        int t0 = m0 & 511;
        float* rowbase = g_Gx + (size_t)(t0 * 64 + bidx) * G4 + c0 + wn * 64;
#pragma unroll
        for (int j = 0; j < 4; j++)
            wmma::store_matrix_sync(rowbase + j * 16, acc[i][j],
                                    (unsigned)(64 * G4), wmma::mem_row_major);
    }
}

// ---------------------------------------------------------------------------
// Phase 2: persistent kernel (UNCHANGED from R11 — known good at 6.84ms).
// ---------------------------------------------------------------------------
__device__ __forceinline__ float sigf(float v) {
    return __fdividef(1.f, 1.f + __expf(-v));
}
__device__ __forceinline__ float tanhfast(float v) {
    float ex = __expf(2.f * v);
    return 1.f - __fdividef(2.f, ex + 1.f);
}

__global__ __launch_bounds__(THREADS, 1) void k_lstm(
    const float* __restrict__ Wf, const float* __restrict__ Wi,
    const float* __restrict__ Wc, const float* __restrict__ Wo,
    const float* __restrict__ bfv, const float* __restrict__ biv,
    const float* __restrict__ bcv, const float* __restrict__ bov,
    float* __restrict__ out)
{
    extern __shared__ float smem[];
    float*  sW    = smem;                          // [1024][SWP] fp32 weights
    float*  sP    = smem + 1024 * SWP;             // [8][64][SPP] dense partials
    float*  sAcc  = sP + 8 * 64 * SPP;             // [64][ACP] accumulator
    float2* sStg  = (float2*)(sAcc + 64 * ACP);    // [8][32] apply staging

    __shared__ float sBias[NC];

    const int tid  = threadIdx.x;
    const int warp = tid >> 5;
    const int lane = tid & 31;
    const int h0   = blockIdx.x * HB;

    for (int k = tid; k < 1024; k += THREADS) {
#pragma unroll
        for (int g = 0; g < 4; g++) {
            const float* W = (g == 0) ? Wf : (g == 1) ? Wi : (g == 2) ? Wc : Wo;
            float4 v0 = *reinterpret_cast<const float4*>(W + (size_t)k * 1024 + h0);
            float4 v1 = *reinterpret_cast<const float4*>(W + (size_t)k * 1024 + h0 + 4);
            float* d = &sW[k * SWP + g * 8];
            d[0] = v0.x; d[1] = v0.y; d[2] = v0.z; d[3] = v0.w;
            d[4] = v1.x; d[5] = v1.y; d[6] = v1.z; d[7] = v1.w;
        }
    }
    if (tid < NC) {
        int g = tid >> 3, hh = tid & 7;
        const float* bv = (g == 0) ? bfv : (g == 1) ? biv : (g == 2) ? bcv : bov;
        sBias[tid] = bv[h0 + hh];
    }
    __syncthreads();

    float creg[2] = {0.f, 0.f};
    float hreg[2] = {0.f, 0.f};

    float gx[2][4];
#pragma unroll
    for (int l = 0; l < 2; l++) {
        int e = tid + l * THREADS;
        int b = e >> 3, hh = e & 7;
        const float* gp = g_Gx + (size_t)b * G4 + h0 + hh;
#pragma unroll
        for (int g = 0; g < 4; g++) gx[l][g] = __ldcg(gp + g * 1024);
    }

    for (int t = 0; t < SEQ; ++t) {
        if (blockIdx.x < BATCH && tid == 0)
            atomicExch(&g_lcnt[(t + 1) % 3][blockIdx.x], 0);

        const bool dense = (t < TD);

        if (t > 0) {
            if (dense) {
                const float* __restrict__ hin = g_hbuf[(t + 1) & 1];
                const int kbase = warp * 128;

                wmma::fragment<wmma::accumulator, 16, 16, 8, float> acc[4][2];
#pragma unroll
                for (int i = 0; i < 4; i++) {
                    wmma::fill_fragment(acc[i][0], 0.f);
                    wmma::fill_fragment(acc[i][1], 0.f);
                }
#pragma unroll 4
                for (int kk = 0; kk < 16; ++kk) {
                    const int k0 = kbase + kk * 8;
                    wmma::fragment<wmma::matrix_b, 16, 16, 8, wmma::precision::tf32, wmma::row_major> bfr[2];
                    wmma::load_matrix_sync(bfr[0], &sW[k0 * SWP], SWP);
                    wmma::load_matrix_sync(bfr[1], &sW[k0 * SWP + 16], SWP);
#pragma unroll
                    for (int e = 0; e < bfr[0].num_elements; e++) {
                        bfr[0].x[e] = wmma::__float_to_tf32(bfr[0].x[e]);
                        bfr[1].x[e] = wmma::__float_to_tf32(bfr[1].x[e]);
                    }
                    wmma::fragment<wmma::matrix_a, 16, 16, 8, wmma::precision::tf32, wmma::row_major> af[4];
#pragma unroll
                    for (int i = 0; i < 4; i++) {
                        wmma::load_matrix_sync(af[i], hin + (size_t)(i * 16) * 1024 + k0, 1024);
#pragma unroll
                        for (int e = 0; e < af[i].num_elements; e++)
                            af[i].x[e] = wmma::__float_to_tf32(af[i].x[e]);
                        wmma::mma_sync(acc[i][0], af[i], bfr[0], acc[i][0]);
                        wmma::mma_sync(acc[i][1], af[i], bfr[1], acc[i][1]);
                    }
                }
#pragma unroll
                for (int i = 0; i < 4; i++)
#pragma unroll
                    for (int j = 0; j < 2; j++)
                        wmma::store_matrix_sync(&sP[warp * (64 * SPP) + (i * 16) * SPP + j * 16],
                                                acc[i][j], SPP, wmma::mem_row_major);
                __syncthreads();
            } else {
                const int ph = (t + 2) % 3;
                const int b0 = warp << 3;
                int myc = (lane < 8) ? __ldcg(&g_lcnt[ph][b0 + lane]) : 0;
                int n[8];
#pragma unroll
                for (int bb = 0; bb < 8; bb++)
                    n[bb] = __shfl_sync(0xffffffffu, myc, bb);

                float acc8[8];
#pragma unroll
                for (int bb = 0; bb < 8; bb++)
                    acc8[bb] = sAcc[(b0 + bb) * ACP + lane];

                float2 pre[8];
#pragma unroll
                for (int bb = 0; bb < 8; bb++)
                    pre[bb] = (lane < n[bb])
                        ? __ldcg(&g_blist[ph][b0 + bb][lane])
                        : make_float2(0.f, 0.f);

                float2* stg = &sStg[warp * 32];
#pragma unroll
                for (int bb = 0; bb < 8; bb++) {
                    int nb = n[bb];
                    float2 cur = pre[bb];
                    for (int base = 0; base < nb; base += 32) {
                        stg[lane] = cur;
                        __syncwarp();
                        if (base + 32 < nb)
                            cur = (lane < nb - base - 32)
                                ? __ldcg(&g_blist[ph][b0 + bb][base + 32 + lane])
                                : make_float2(0.f, 0.f);
                        int cnt = min(32, nb - base);
                        for (int j = 0; j < cnt; ++j) {
                            float2 E = stg[j];
                            acc8[bb] += E.y * sW[__float_as_int(E.x) * SWP + lane];
                        }
                        __syncwarp();
                    }
                }
#pragma unroll
                for (int bb = 0; bb < 8; bb++)
                    sAcc[(b0 + bb) * ACP + lane] = acc8[bb];
                __syncthreads();
            }
        }

        float* __restrict__ hnew = g_hbuf[t & 1];
        float outv[2];
        bool emitted = false;
#pragma unroll
        for (int l = 0; l < 2; l++) {
            int e  = tid + l * THREADS;
            int b  = e >> 3, hh = e & 7;
            int h  = h0 + hh;

            float s0, s1, s2, s3;
            if (dense) {
                s0 = s1 = s2 = s3 = 0.f;
                if (t > 0) {
#pragma unroll
                    for (int w = 0; w < 8; w++) {
                        const float* p = &sP[w * (64 * SPP) + b * SPP];
                        s0 += p[hh];
                        s1 += p[8 + hh];
                        s2 += p[16 + hh];
                        s3 += p[24 + hh];
                    }
                }
                sAcc[b * ACP + hh]      = s0;
                sAcc[b * ACP + 8 + hh]  = s1;
                sAcc[b * ACP + 16 + hh] = s2;
                sAcc[b * ACP + 24 + hh] = s3;
            } else {
                s0 = sAcc[b * ACP + hh];
                s1 = sAcc[b * ACP + 8 + hh];
                s2 = sAcc[b * ACP + 16 + hh];
                s3 = sAcc[b * ACP + 24 + hh];
            }

            float gf = s0 + gx[l][0] + sBias[hh];
            float gi = s1 + gx[l][1] + sBias[8 + hh];
            float gc = s2 + gx[l][2] + sBias[16 + hh];
            float go = s3 + gx[l][3] + sBias[24 + hh];

            float Cn = sigf(gf) * creg[l] + sigf(gi) * tanhfast(gc);
            creg[l] = Cn;
            float hv = sigf(go) * tanhfast(Cn);
            outv[l] = hv;

            if (t >= TD - 1 && t < SEQ - 1 && hv > hreg[l]) {
                float dlt = hv - hreg[l];
                int pos = atomicAdd(&g_lcnt[t % 3][b], 1);
                g_blist[t % 3][b][pos] = make_float2(__int_as_float(h), dlt);
                emitted = true;
            }
            float hm = (t == 0) ? hv : fmaxf(hreg[l], hv);
            hreg[l] = hm;

            if (t < TD - 1) hnew[b * HID + h] = hm;

            if (t == SEQ - 1) {
                out[(size_t)b * SEQ * HID + (size_t)t * HID + h] = hv;
                out[(size_t)BSH + b * HID + h] = hm;                     // h_fin
                out[(size_t)BSH + BATCH * HID + b * HID + h] = Cn;       // C_fin
            }
        }

        if (t < SEQ - 1) {
            if (dense || emitted) __threadfence();
            __syncthreads();
            unsigned arr = 0;
            if (tid == 0) arr = atomicAdd(&g_bar[t], 1u) + 1;

#pragma unroll
            for (int l = 0; l < 2; l++) {
                int e = tid + l * THREADS;
                int b = e >> 3, hh = e & 7;
                out[(size_t)b * SEQ * HID + (size_t)t * HID + h0 + hh] = outv[l];
            }
#pragma unroll
            for (int l = 0; l < 2; l++) {
                int e = tid + l * THREADS;
                int b = e >> 3, hh = e & 7;
                const float* gp = g_Gx + (size_t)((t + 1) * 64 + b) * G4 + h0 + hh;
#pragma unroll
                for (int g = 0; g < 4; g++) gx[l][g] = __ldcg(gp + g * 1024);
            }

            if (tid == 0) {
                if (arr == CTAS) {
                    __stcg(&g_rel[t], 1u);
                } else {
                    volatile unsigned* p = &g_rel[t];
                    while (*p == 0u) { }
                }
                if (t + 1 < TD) __threadfence();
            }
            __syncthreads();
        }
    }
}

extern "C" void kernel_launch(void* const* d_in, const int* in_sizes, int n_in,
                              void* d_out, int out_size) {
    const float* x  = (const float*)d_in[0];
    const float* Wf = (const float*)d_in[1];
    const float* bf = (const float*)d_in[2];
    const float* Wi = (const float*)d_in[3];
    const float* bi = (const float*)d_in[4];
    const float* Wc = (const float*)d_in[5];
    const float* bc = (const float*)d_in[6];
    const float* Wo = (const float*)d_in[7];
    const float* bo = (const float*)d_in[8];
    float* out = (float*)d_out;

    static const size_t SMEM_L =
        (1024 * SWP + 8 * 64 * SPP + 64 * ACP) * sizeof(float) + 8 * 32 * sizeof(float2);
    static const size_t SMEM_G =
        (4 * 128 * XAP + 4 * 32 * XBP) * sizeof(__nv_bfloat16);   // 75,776 B
    cudaFuncSetAttribute(k_lstm,   cudaFuncAttributeMaxDynamicSharedMemorySize, (int)SMEM_L);
    cudaFuncSetAttribute(k_gemm_x, cudaFuncAttributeMaxDynamicSharedMemorySize, (int)SMEM_G);

    k_cvt<<<8192, 256>>>(x, Wf, Wi, Wc, Wo);
    k_gemm_x<<<dim3(32, 256), 256, SMEM_G>>>();
    k_lstm<<<CTAS, THREADS, SMEM_L>>>(Wf, Wi, Wc, Wo, bf, bi, bc, bo, out);
}